// round 16
// baseline (speedup 1.0000x reference)
#include <cuda_runtime.h>
#include <math.h>

#define NS 2048
#define NR 2048
#define KNB 5
#define NBINS 1024
#define RFLOOR 960                 // scan1 bins only v >= 0.9375 (bin 960+)
#define GATEF 0.9375f              // 960/1024, exact bin edge
#define COLLECT_BIN 993
#define COLLECT_THR 0.9697265625f  // 993/1024, exact bin edge
#define CAP 65536
#define KEYS_CAP 4096
#define MAXIDX 104857599u
#define KNN_QPB 8
// float32 nearest to python 0.1**2
#define SIG2F 0.009999999776482582f

__device__ float    g_sd[NS*KNB];
__device__ int      g_sidx[NS*KNB];
__device__ float    g_rdT[KNB*NR];
__device__ int      g_ridxT[KNB*NR];
__device__ unsigned g_hist[NBINS];
__device__ unsigned g_ccount;
__device__ float    g_thr;
__device__ int      g_skip;
__device__ int      g_need_full;
__device__ unsigned g_done;
__device__ unsigned g_done2;
__device__ float    g_cval[CAP];
__device__ int      g_cidx[CAP];

// FMA-CONTRACTED squared distance — matches XLA's contraction (verified R11).
__device__ __forceinline__ float d2_ref(float dx, float dy, float dz) {
    return __fmaf_rn(dz, dz, __fmaf_rn(dy, dy, __fmul_rn(dx, dx)));
}

// KNN (proven R13 core) + state reset duties (replaces zero_kernel).
// blocks [0, 256) -> src (mode 0), blocks [256, 512) -> ref (mode 1).
__global__ __launch_bounds__(256) void knn_kernel(const float* __restrict__ src,
                                                  const float* __restrict__ ref) {
    __shared__ float sp[3 * 2048];
    int tid = threadIdx.x;
    // reset duties (visible at kernel boundary, before scan1)
    if (blockIdx.x < 4) {
        for (int b = blockIdx.x * 256 + tid; b < NBINS; b += 1024) g_hist[b] = 0;
    }
    if (blockIdx.x == 0 && tid == 0) {
        g_ccount = 0; g_need_full = 0; g_skip = 0; g_done = 0; g_done2 = 0;
    }
    int mode = (blockIdx.x >= (NS / KNN_QPB)) ? 1 : 0;
    const float* pts = mode ? ref : src;
    int bq = mode ? (blockIdx.x - NS / KNN_QPB) : blockIdx.x;
    const int n = 2048;
    for (int t = tid; t < 3 * n; t += 256) sp[t] = pts[t];
    __syncthreads();
    int warp = tid >> 5, lane = tid & 31;
    int q = bq * KNN_QPB + warp;
    float px = sp[q * 3], py = sp[q * 3 + 1], pz = sp[q * 3 + 2];
    unsigned long long best[6];
#pragma unroll
    for (int t = 0; t < 6; t++) best[t] = 0xFFFFFFFFFFFFFFFFULL;
    for (int j = lane; j < n; j += 32) {
        float d2 = d2_ref(sp[j * 3] - px, sp[j * 3 + 1] - py, sp[j * 3 + 2] - pz);
        float dist = __fsqrt_rn(fmaxf(d2, 0.0f));    // jax's ranking key
        unsigned long long key =
            ((unsigned long long)__float_as_uint(dist) << 32) | (unsigned)j;
        if (key < best[5]) {
            best[5] = key;
#pragma unroll
            for (int t = 5; t > 0; t--) {
                if (best[t] < best[t - 1]) {
                    unsigned long long tmp = best[t];
                    best[t] = best[t - 1]; best[t - 1] = tmp;
                }
            }
        }
    }
    unsigned long long res[6];
    int h = 0;
#pragma unroll
    for (int t = 0; t < 6; t++) {
        unsigned long long cand = (h < 6) ? best[h] : 0xFFFFFFFFFFFFFFFFULL;
        unsigned long long mn = cand;
#pragma unroll
        for (int o = 16; o > 0; o >>= 1) {
            unsigned long long other = __shfl_xor_sync(0xFFFFFFFFu, mn, o);
            if (other < mn) mn = other;
        }
        if (cand == mn) h++;
        res[t] = mn;
    }
    if (lane >= 1 && lane <= 5) {      // drop rank 0 (self)
        unsigned long long key = res[lane];
        float dist = __uint_as_float((unsigned)(key >> 32));
        int ni = (int)(key & 0x7FFFFFFFu);
        if (ni >= n) ni = n - 1;
        int c = lane - 1;
        if (mode == 0) { g_sd[q * KNB + c] = dist; g_sidx[q * KNB + c] = ni; }
        else           { g_rdT[c * NR + q] = dist; g_ridxT[c * NR + q] = ni; }
    }
}

// SCAN v5: compaction + direct L2 gathers (proven R15) + EMBEDDED threshold
// in the last-finishing block (done-counter), reading the 64 bins in parallel.
__global__ __launch_bounds__(256) void scan1_kernel(const float* __restrict__ aff) {
    __shared__ int      rlist[2048];
    __shared__ float    rbase[2048];
    __shared__ unsigned hist[NBINS - RFLOOR];
    __shared__ int      s_sidx[KNB];
    __shared__ unsigned rcnt;
    __shared__ int      lastflag;
    int s = blockIdx.x, tid = threadIdx.x;
    if (tid < KNB) s_sidx[tid] = g_sidx[s * KNB + tid];
    if (tid == 0) rcnt = 0;
    for (int b = tid; b < NBINS - RFLOOR; b += 256) hist[b] = 0;
    __syncthreads();
    // Phase A: coalesced float4 base sweep + compaction (exact gate)
    const float4* bp = (const float4*)(aff + s * NR);
    for (int c = tid; c < 512; c += 256) {
        float4 b4 = bp[c];
        if (b4.x >= GATEF) { unsigned p = atomicAdd(&rcnt, 1u); rlist[p] = c*4+0; rbase[p] = b4.x; }
        if (b4.y >= GATEF) { unsigned p = atomicAdd(&rcnt, 1u); rlist[p] = c*4+1; rbase[p] = b4.y; }
        if (b4.z >= GATEF) { unsigned p = atomicAdd(&rcnt, 1u); rlist[p] = c*4+2; rbase[p] = b4.z; }
        if (b4.w >= GATEF) { unsigned p = atomicAdd(&rcnt, 1u); rlist[p] = c*4+3; rbase[p] = b4.w; }
    }
    float sdv[KNB];
#pragma unroll
    for (int i = 0; i < KNB; i++) sdv[i] = g_sd[s * KNB + i];
    __syncthreads();
    int rowb[KNB];
#pragma unroll
    for (int i = 0; i < KNB; i++) rowb[i] = s_sidx[i] * NR;
    int cnt = rcnt;
    // Phase B: thread-per-survivor, 25 unconditional combos, direct L2 gathers
    for (int k = tid; k < cnt; k += 256) {
        int r = rlist[k];
        float base = rbase[k];
        float b100 = -100.0f * base;
        float rd[KNB]; int ra[KNB];
#pragma unroll
        for (int j = 0; j < KNB; j++) {
            rd[j] = g_rdT[j * NR + r];
            ra[j] = g_ridxT[j * NR + r];
        }
        float a2v[KNB][KNB];
#pragma unroll
        for (int i = 0; i < KNB; i++)
#pragma unroll
            for (int j = 0; j < KNB; j++)
                a2v[i][j] = __ldg(&aff[rowb[i] + ra[j]]);
#pragma unroll
        for (int i = 0; i < KNB; i++) {
#pragma unroll
            for (int j = 0; j < KNB; j++) {
                float d  = sdv[i] - rd[j];
                float dd = __fmul_rn(d, d);
                float bt = __fmaf_rn(dd, b100, base);
                float v  = __fmul_rn(bt, a2v[i][j]);
                if (v >= GATEF) {
                    int bin = (int)(v * 1024.0f);     // exact pow2 binning
                    if (bin > NBINS - 1) bin = NBINS - 1;
                    atomicAdd(&hist[bin - RFLOOR], 1u);
                    if (v >= COLLECT_THR) {
                        float qq  = __fdiv_rn(dd, SIG2F);
                        float tmp = __fadd_rn(1.0f, -qq);
                        tmp = fmaxf(tmp, 0.0f);
                        float vf = __fmul_rn(__fmul_rn(base, tmp), a2v[i][j]);
                        unsigned pos = atomicAdd(&g_ccount, 1u);
                        if (pos < CAP) {
                            g_cval[pos] = vf;
                            g_cidx[pos] = (s * NR + r) * 25 + i * 5 + j;
                        }
                    }
                }
            }
        }
    }
    __syncthreads();
    for (int b = tid; b < NBINS - RFLOOR; b += 256) {
        unsigned c = hist[b];
        if (c) atomicAdd(&g_hist[RFLOOR + b], c);
    }
    // Embedded threshold: last block to finish computes it.
    __threadfence();
    if (tid == 0)
        lastflag = (atomicAdd(&g_done, 1u) == gridDim.x - 1) ? 1 : 0;
    __syncthreads();
    if (lastflag) {
        if (tid < NBINS - RFLOOR)
            hist[tid] = atomicAdd(&g_hist[RFLOOR + tid], 0u);  // parallel L2 reads
        __syncthreads();
        if (tid == 0) {
            unsigned suf = 0; int bstar = -1;
            for (int b = NBINS - 1; b >= RFLOOR; b--) {
                suf += hist[b - RFLOOR];
                if (suf >= 512) { bstar = b; break; }
            }
            if (bstar <= RFLOOR) {
                g_need_full = 1;
                g_skip = 0;
            } else {
                int ba = bstar - 1;        // one-bin slack
                unsigned cnt2 = suf + hist[ba - RFLOOR];
                while (cnt2 > CAP && ba < NBINS - 1) {
                    cnt2 -= hist[ba - RFLOOR];
                    ba++;
                }
                g_thr = (float)ba * (1.0f / 1024.0f);
                int skip = (ba >= COLLECT_BIN &&
                            atomicAdd(&g_ccount, 0u) <= CAP) ? 1 : 0;
                g_skip = skip;
                if (!skip) g_ccount = 0;
            }
        }
    }
}

// Conditional full low-bin histogram [0, RFLOOR) + EMBEDDED re-threshold in
// the last block. Done-counter incremented unconditionally (idle path drains).
__global__ __launch_bounds__(256) void hist_low_kernel(const float* __restrict__ aff) {
    __shared__ float    rows[KNB][2048];
    __shared__ unsigned hist[RFLOOR];
    __shared__ unsigned hfull[NBINS];
    __shared__ int      s_sidx[KNB];
    __shared__ int      lastflag;
    int s = blockIdx.x, tid = threadIdx.x;
    int need = g_need_full;
    if (need) {
        if (tid < KNB) s_sidx[tid] = g_sidx[s * KNB + tid];
        for (int b = tid; b < RFLOOR; b += 256) hist[b] = 0;
        __syncthreads();
#pragma unroll
        for (int i = 0; i < KNB; i++) {
            const float4* srcp = (const float4*)(aff + s_sidx[i] * NR);
            float4* dst = (float4*)rows[i];
            for (int c = tid; c < 512; c += 256) dst[c] = srcp[c];
        }
        float sdv[KNB];
#pragma unroll
        for (int i = 0; i < KNB; i++) sdv[i] = g_sd[s * KNB + i];
        __syncthreads();
        for (int rb = 0; rb < NR; rb += 256) {
            int r = rb + tid;
            float base = aff[s * NR + r];
            float b100 = -100.0f * base;
            float rd[KNB]; int ra[KNB];
#pragma unroll
            for (int j = 0; j < KNB; j++) {
                rd[j] = g_rdT[j * NR + r];
                ra[j] = g_ridxT[j * NR + r];
            }
#pragma unroll
            for (int i = 0; i < KNB; i++) {
#pragma unroll
                for (int j = 0; j < KNB; j++) {
                    float d  = sdv[i] - rd[j];
                    float bt = __fmaf_rn(__fmul_rn(d, d), b100, base);
                    float v  = __fmul_rn(bt, rows[i][ra[j]]);
                    if (v > 0.0f && v < GATEF) {
                        int bin = (int)(v * 1024.0f);
                        if (bin < RFLOOR) atomicAdd(&hist[bin], 1u);
                    }
                }
            }
        }
        __syncthreads();
        for (int b = tid; b < RFLOOR; b += 256) {
            unsigned c = hist[b];
            if (c) atomicAdd(&g_hist[b], c);
        }
    }
    __threadfence();
    if (tid == 0)
        lastflag = (atomicAdd(&g_done2, 1u) == gridDim.x - 1) ? 1 : 0;
    __syncthreads();
    if (lastflag && need) {
        for (int b = tid; b < NBINS; b += 256)
            hfull[b] = atomicAdd(&g_hist[b], 0u);
        __syncthreads();
        if (tid == 0) {
            unsigned suf = 0; int bstar = -1;
            for (int b = NBINS - 1; b >= 0; b--) {
                suf += hfull[b];
                if (suf >= 512) { bstar = b; break; }
            }
            if (bstar < 0) bstar = 0;
            int ba = bstar > 0 ? bstar - 1 : 0;
            unsigned cnt = suf + ((ba < bstar) ? hfull[ba] : 0u);
            while (cnt > CAP && ba < NBINS - 1) {
                cnt -= hfull[ba];
                ba++;
            }
            float thr = (float)ba * (1.0f / 1024.0f);
            if (thr < 1e-30f) thr = 1e-30f;
            g_thr = thr;
            g_skip = 0;
            g_ccount = 0;
        }
    }
}

// Fallback collect (usually skipped): admit hot v >= thr, store faithful value.
__global__ __launch_bounds__(256) void collect_kernel(const float* __restrict__ aff) {
    if (g_skip) return;
    __shared__ float rows[KNB][2048];
    __shared__ int   s_sidx[KNB];
    int s = blockIdx.x, tid = threadIdx.x;
    if (tid < KNB) s_sidx[tid] = g_sidx[s * KNB + tid];
    __syncthreads();
#pragma unroll
    for (int i = 0; i < KNB; i++) {
        const float4* srcp = (const float4*)(aff + s_sidx[i] * NR);
        float4* dst = (float4*)rows[i];
        for (int c = tid; c < 512; c += 256) dst[c] = srcp[c];
    }
    float thr = g_thr;
    float sdv[KNB];
#pragma unroll
    for (int i = 0; i < KNB; i++) sdv[i] = g_sd[s * KNB + i];
    __syncthreads();
    for (int rb = 0; rb < NR; rb += 256) {
        int r = rb + tid;
        float base = aff[s * NR + r];
        float b100 = -100.0f * base;
        float rd[KNB]; int ra[KNB];
#pragma unroll
        for (int j = 0; j < KNB; j++) {
            rd[j] = g_rdT[j * NR + r];
            ra[j] = g_ridxT[j * NR + r];
        }
#pragma unroll
        for (int i = 0; i < KNB; i++) {
#pragma unroll
            for (int j = 0; j < KNB; j++) {
                float d  = sdv[i] - rd[j];
                float dd = __fmul_rn(d, d);
                float bt = __fmaf_rn(dd, b100, base);
                if (bt >= thr) {
                    float v = __fmul_rn(bt, rows[i][ra[j]]);
                    if (v >= thr && v > 0.0f) {
                        float qq  = __fdiv_rn(dd, SIG2F);
                        float tmp = __fadd_rn(1.0f, -qq);
                        tmp = fmaxf(tmp, 0.0f);
                        float vf = __fmul_rn(__fmul_rn(base, tmp), rows[i][ra[j]]);
                        unsigned pos = atomicAdd(&g_ccount, 1u);
                        if (pos < CAP) {
                            g_cval[pos] = vf;
                            g_cidx[pos] = (s * NR + r) * 25 + i * 5 + j;
                        }
                    }
                }
            }
        }
    }
}

// Select: refine (exact capacity check) -> DYNAMIC-width bitonic sort
// (value desc, index asc) -> emit f32 indices.
__global__ __launch_bounds__(1024) void select_kernel(float* __restrict__ out,
                                                      int out_size) {
    __shared__ unsigned long long keys[KEYS_CAP];
    __shared__ unsigned h2[1024];
    __shared__ unsigned m2;
    __shared__ float sh_thr2;
    int tid = threadIdx.x;
    unsigned M = g_ccount; if (M > CAP) M = CAP;
    float thr = g_thr;
    h2[tid] = 0;
    if (tid == 0) { m2 = 0; sh_thr2 = -1.0f; }
    __syncthreads();
    if (M > KEYS_CAP) {
        float binw2 = (1.0f - thr) * (1.0f / 1024.0f);
        if (binw2 <= 0.0f) binw2 = 1e-9f;
        for (unsigned c = tid; c < M; c += 1024) {
            float v = g_cval[c];
            int b = (int)((v - thr) / binw2);
            if (b < 0) b = 0;
            if (b > 1023) b = 1023;
            atomicAdd(&h2[b], 1u);
        }
        __syncthreads();
        if (tid == 0) {
            unsigned suf = 0; int b2 = 0;
            for (int b = 1023; b >= 0; b--) {
                suf += h2[b];
                if (suf >= 512) { b2 = b; break; }
            }
            int ba = b2;
            unsigned cnt = suf;
            if (ba > 0 && cnt + h2[ba - 1] <= (unsigned)KEYS_CAP) {
                ba--; cnt += h2[ba];
            }
            while (cnt > (unsigned)KEYS_CAP && ba < 1023) {
                cnt -= h2[ba]; ba++;
            }
            sh_thr2 = thr + (float)ba * binw2;
            if (sh_thr2 < thr) sh_thr2 = thr;
        }
        __syncthreads();
    }
    float thr2 = sh_thr2;   // -1 => keep all
    for (unsigned c = tid; c < M; c += 1024) {
        float v = g_cval[c];
        if (v >= thr2) {
            unsigned p = atomicAdd(&m2, 1u);
            if (p < KEYS_CAP) {
                unsigned idx = (unsigned)g_cidx[c];
                if (idx > MAXIDX) idx = MAXIDX;
                keys[p] = ((unsigned long long)__float_as_uint(v) << 32)
                        | (unsigned long long)(0xFFFFFFFFu - idx);
            }
        }
    }
    __syncthreads();
    unsigned M2 = m2; if (M2 > KEYS_CAP) M2 = KEYS_CAP;
    unsigned SORT = 512;
    while (SORT < M2) SORT <<= 1;           // <= KEYS_CAP since M2 <= KEYS_CAP
    for (unsigned e = M2 + tid; e < SORT; e += 1024) keys[e] = 0ull;
    __syncthreads();
    for (unsigned k = 2; k <= SORT; k <<= 1) {
        for (unsigned jj = k >> 1; jj > 0; jj >>= 1) {
            for (unsigned e = tid; e < SORT; e += 1024) {
                unsigned partner = e ^ jj;
                if (partner > e) {
                    unsigned long long A = keys[e], B = keys[partner];
                    bool desc = ((e & k) == 0);
                    if (desc ? (A < B) : (A > B)) { keys[e] = B; keys[partner] = A; }
                }
            }
            __syncthreads();
        }
    }
    if (tid < 512) {
        unsigned long long key = keys[tid];
        unsigned idx = 0xFFFFFFFFu - (unsigned)(key & 0xFFFFFFFFull);
        if (idx > MAXIDX) idx = MAXIDX;
        int s = (int)(idx / 51200u);  int rem = (int)(idx - (unsigned)s * 51200u);
        int r = rem / 25;             int ij  = rem - r * 25;
        int i = ij / 5;               int j   = ij - i * 5;
        if (s > NS - 1) s = NS - 1;
        if (r > NR - 1) r = NR - 1;
        if (tid < out_size)        out[tid]        = (float)s;
        if (512 + tid < out_size)  out[512 + tid]  = (float)r;
        if (1024 + tid < out_size) out[1024 + tid] = (float)g_sidx[s * KNB + i];
        if (1536 + tid < out_size) out[1536 + tid] = (float)g_ridxT[j * NR + r];
    }
}

extern "C" void kernel_launch(void* const* d_in, const int* in_sizes, int n_in,
                              void* d_out, int out_size) {
    const float *src, *ref, *aff;
    if (in_sizes[0] >= (1 << 20)) {
        aff = (const float*)d_in[0];
        ref = (const float*)d_in[1];
        src = (const float*)d_in[2];
    } else {
        src = (const float*)d_in[0];
        ref = (const float*)d_in[1];
        aff = (const float*)d_in[2];
    }
    float* out = (float*)d_out;

    knn_kernel<<<(NS + NR) / KNN_QPB, 256>>>(src, ref);   // + state reset
    scan1_kernel<<<NS, 256>>>(aff);                       // + embedded threshold
    hist_low_kernel<<<NS, 256>>>(aff);                    // idle normally; + thresh2
    collect_kernel<<<NS, 256>>>(aff);                     // idle normally
    select_kernel<<<1, 1024>>>(out, out_size);
}

// round 17
// speedup vs baseline: 1.0506x; 1.0506x over previous
#include <cuda_runtime.h>
#include <math.h>

#define NS 2048
#define NR 2048
#define KNB 5
#define NBINS 1024
#define RFLOOR 960                 // scan1 bins only v >= 0.9375 (bin 960+)
#define GATEF 0.9375f              // 960/1024, exact bin edge
#define COLLECT_BIN 993
#define COLLECT_THR 0.9697265625f  // 993/1024, exact bin edge
#define CAP 65536
#define KEYS_CAP 4096
#define MAXIDX 104857599u
#define KNN_QPB 8
#define FB_GRID 256                // fallback kernels: small grid, s-loop
// float32 nearest to python 0.1**2
#define SIG2F 0.009999999776482582f

__device__ float    g_sd[NS*KNB];
__device__ int      g_sidx[NS*KNB];
__device__ float    g_rdT[KNB*NR];
__device__ int      g_ridxT[KNB*NR];
__device__ unsigned g_hist[NBINS];
__device__ unsigned g_ccount;
__device__ float    g_thr;
__device__ int      g_skip;
__device__ int      g_need_full;
__device__ float    g_cval[CAP];
__device__ int      g_cidx[CAP];

// FMA-CONTRACTED squared distance — matches XLA's contraction (verified R11).
__device__ __forceinline__ float d2_ref(float dx, float dy, float dz) {
    return __fmaf_rn(dz, dz, __fmaf_rn(dy, dy, __fmul_rn(dx, dx)));
}

// KNN (proven R13 core) + state reset duties (replaces zero_kernel).
__global__ __launch_bounds__(256) void knn_kernel(const float* __restrict__ src,
                                                  const float* __restrict__ ref) {
    __shared__ float sp[3 * 2048];
    int tid = threadIdx.x;
    if (blockIdx.x < 4) {
        for (int b = blockIdx.x * 256 + tid; b < NBINS; b += 1024) g_hist[b] = 0;
    }
    if (blockIdx.x == 0 && tid == 0) {
        g_ccount = 0; g_need_full = 0; g_skip = 0;
    }
    int mode = (blockIdx.x >= (NS / KNN_QPB)) ? 1 : 0;
    const float* pts = mode ? ref : src;
    int bq = mode ? (blockIdx.x - NS / KNN_QPB) : blockIdx.x;
    const int n = 2048;
    for (int t = tid; t < 3 * n; t += 256) sp[t] = pts[t];
    __syncthreads();
    int warp = tid >> 5, lane = tid & 31;
    int q = bq * KNN_QPB + warp;
    float px = sp[q * 3], py = sp[q * 3 + 1], pz = sp[q * 3 + 2];
    unsigned long long best[6];
#pragma unroll
    for (int t = 0; t < 6; t++) best[t] = 0xFFFFFFFFFFFFFFFFULL;
    for (int j = lane; j < n; j += 32) {
        float d2 = d2_ref(sp[j * 3] - px, sp[j * 3 + 1] - py, sp[j * 3 + 2] - pz);
        float dist = __fsqrt_rn(fmaxf(d2, 0.0f));    // jax's ranking key
        unsigned long long key =
            ((unsigned long long)__float_as_uint(dist) << 32) | (unsigned)j;
        if (key < best[5]) {
            best[5] = key;
#pragma unroll
            for (int t = 5; t > 0; t--) {
                if (best[t] < best[t - 1]) {
                    unsigned long long tmp = best[t];
                    best[t] = best[t - 1]; best[t - 1] = tmp;
                }
            }
        }
    }
    unsigned long long res[6];
    int h = 0;
#pragma unroll
    for (int t = 0; t < 6; t++) {
        unsigned long long cand = (h < 6) ? best[h] : 0xFFFFFFFFFFFFFFFFULL;
        unsigned long long mn = cand;
#pragma unroll
        for (int o = 16; o > 0; o >>= 1) {
            unsigned long long other = __shfl_xor_sync(0xFFFFFFFFu, mn, o);
            if (other < mn) mn = other;
        }
        if (cand == mn) h++;
        res[t] = mn;
    }
    if (lane >= 1 && lane <= 5) {      // drop rank 0 (self)
        unsigned long long key = res[lane];
        float dist = __uint_as_float((unsigned)(key >> 32));
        int ni = (int)(key & 0x7FFFFFFFu);
        if (ni >= n) ni = n - 1;
        int c = lane - 1;
        if (mode == 0) { g_sd[q * KNB + c] = dist; g_sidx[q * KNB + c] = ni; }
        else           { g_rdT[c * NR + q] = dist; g_ridxT[c * NR + q] = ni; }
    }
}

// SCAN v4 (proven R15): compaction + direct L2 gathers. No embedded thresh.
__global__ __launch_bounds__(256) void scan1_kernel(const float* __restrict__ aff) {
    __shared__ int      rlist[2048];
    __shared__ float    rbase[2048];
    __shared__ unsigned hist[NBINS - RFLOOR];
    __shared__ int      s_sidx[KNB];
    __shared__ unsigned rcnt;
    int s = blockIdx.x, tid = threadIdx.x;
    if (tid < KNB) s_sidx[tid] = g_sidx[s * KNB + tid];
    if (tid == 0) rcnt = 0;
    for (int b = tid; b < NBINS - RFLOOR; b += 256) hist[b] = 0;
    __syncthreads();
    const float4* bp = (const float4*)(aff + s * NR);
    for (int c = tid; c < 512; c += 256) {
        float4 b4 = bp[c];
        if (b4.x >= GATEF) { unsigned p = atomicAdd(&rcnt, 1u); rlist[p] = c*4+0; rbase[p] = b4.x; }
        if (b4.y >= GATEF) { unsigned p = atomicAdd(&rcnt, 1u); rlist[p] = c*4+1; rbase[p] = b4.y; }
        if (b4.z >= GATEF) { unsigned p = atomicAdd(&rcnt, 1u); rlist[p] = c*4+2; rbase[p] = b4.z; }
        if (b4.w >= GATEF) { unsigned p = atomicAdd(&rcnt, 1u); rlist[p] = c*4+3; rbase[p] = b4.w; }
    }
    float sdv[KNB];
#pragma unroll
    for (int i = 0; i < KNB; i++) sdv[i] = g_sd[s * KNB + i];
    __syncthreads();
    int rowb[KNB];
#pragma unroll
    for (int i = 0; i < KNB; i++) rowb[i] = s_sidx[i] * NR;
    int cnt = rcnt;
    for (int k = tid; k < cnt; k += 256) {
        int r = rlist[k];
        float base = rbase[k];
        float b100 = -100.0f * base;
        float rd[KNB]; int ra[KNB];
#pragma unroll
        for (int j = 0; j < KNB; j++) {
            rd[j] = g_rdT[j * NR + r];
            ra[j] = g_ridxT[j * NR + r];
        }
        float a2v[KNB][KNB];
#pragma unroll
        for (int i = 0; i < KNB; i++)
#pragma unroll
            for (int j = 0; j < KNB; j++)
                a2v[i][j] = __ldg(&aff[rowb[i] + ra[j]]);
#pragma unroll
        for (int i = 0; i < KNB; i++) {
#pragma unroll
            for (int j = 0; j < KNB; j++) {
                float d  = sdv[i] - rd[j];
                float dd = __fmul_rn(d, d);
                float bt = __fmaf_rn(dd, b100, base);
                float v  = __fmul_rn(bt, a2v[i][j]);
                if (v >= GATEF) {
                    int bin = (int)(v * 1024.0f);     // exact pow2 binning
                    if (bin > NBINS - 1) bin = NBINS - 1;
                    atomicAdd(&hist[bin - RFLOOR], 1u);
                    if (v >= COLLECT_THR) {
                        float qq  = __fdiv_rn(dd, SIG2F);
                        float tmp = __fadd_rn(1.0f, -qq);
                        tmp = fmaxf(tmp, 0.0f);
                        float vf = __fmul_rn(__fmul_rn(base, tmp), a2v[i][j]);
                        unsigned pos = atomicAdd(&g_ccount, 1u);
                        if (pos < CAP) {
                            g_cval[pos] = vf;
                            g_cidx[pos] = (s * NR + r) * 25 + i * 5 + j;
                        }
                    }
                }
            }
        }
    }
    __syncthreads();
    for (int b = tid; b < NBINS - RFLOOR; b += 256) {
        unsigned c = hist[b];
        if (c) atomicAdd(&g_hist[RFLOOR + b], c);
    }
}

// Threshold: PARALLEL bin reads (R15's 5.6us was one thread doing 64 serial
// L2 loads), then one-thread suffix scan on smem.
__global__ void thresh_kernel() {
    __shared__ unsigned h[NBINS - RFLOOR];
    int tid = threadIdx.x;
    if (tid < NBINS - RFLOOR) h[tid] = g_hist[RFLOOR + tid];
    __syncthreads();
    if (tid == 0) {
        unsigned suf = 0; int bstar = -1;
        for (int b = NBINS - 1; b >= RFLOOR; b--) {
            suf += h[b - RFLOOR];
            if (suf >= 512) { bstar = b; break; }
        }
        if (bstar <= RFLOOR) {
            g_need_full = 1;
            g_skip = 0;
            return;
        }
        int ba = bstar - 1;             // one-bin slack
        unsigned cnt = suf + h[ba - RFLOOR];
        while (cnt > CAP && ba < NBINS - 1) {
            cnt -= h[ba - RFLOOR];
            ba++;
        }
        g_thr = (float)ba * (1.0f / 1024.0f);
        int skip = (ba >= COLLECT_BIN && g_ccount <= CAP) ? 1 : 0;
        g_skip = skip;
        if (!skip) g_ccount = 0;
    }
}

// Conditional full low-bin histogram — SMALL GRID + s-loop (cheap when idle).
__global__ __launch_bounds__(256) void hist_low_kernel(const float* __restrict__ aff) {
    if (!g_need_full) return;
    __shared__ float    rows[KNB][2048];
    __shared__ unsigned hist[RFLOOR];
    __shared__ int      s_sidx[KNB];
    int tid = threadIdx.x;
    for (int s = blockIdx.x; s < NS; s += gridDim.x) {
        __syncthreads();
        if (tid < KNB) s_sidx[tid] = g_sidx[s * KNB + tid];
        for (int b = tid; b < RFLOOR; b += 256) hist[b] = 0;
        __syncthreads();
#pragma unroll
        for (int i = 0; i < KNB; i++) {
            const float4* srcp = (const float4*)(aff + s_sidx[i] * NR);
            float4* dst = (float4*)rows[i];
            for (int c = tid; c < 512; c += 256) dst[c] = srcp[c];
        }
        float sdv[KNB];
#pragma unroll
        for (int i = 0; i < KNB; i++) sdv[i] = g_sd[s * KNB + i];
        __syncthreads();
        for (int rb = 0; rb < NR; rb += 256) {
            int r = rb + tid;
            float base = aff[s * NR + r];
            float b100 = -100.0f * base;
            float rd[KNB]; int ra[KNB];
#pragma unroll
            for (int j = 0; j < KNB; j++) {
                rd[j] = g_rdT[j * NR + r];
                ra[j] = g_ridxT[j * NR + r];
            }
#pragma unroll
            for (int i = 0; i < KNB; i++) {
#pragma unroll
                for (int j = 0; j < KNB; j++) {
                    float d  = sdv[i] - rd[j];
                    float bt = __fmaf_rn(__fmul_rn(d, d), b100, base);
                    float v  = __fmul_rn(bt, rows[i][ra[j]]);
                    if (v > 0.0f && v < GATEF) {
                        int bin = (int)(v * 1024.0f);
                        if (bin < RFLOOR) atomicAdd(&hist[bin], 1u);
                    }
                }
            }
        }
        __syncthreads();
        for (int b = tid; b < RFLOOR; b += 256) {
            unsigned c = hist[b];
            if (c) atomicAdd(&g_hist[b], c);
        }
    }
}

// Conditional re-threshold: parallel bin reads, one-thread scan.
__global__ void thresh2_kernel() {
    __shared__ unsigned h[NBINS];
    int tid = threadIdx.x;
    if (!g_need_full) return;
    for (int b = tid; b < NBINS; b += 256) h[b] = g_hist[b];
    __syncthreads();
    if (tid == 0) {
        unsigned suf = 0; int bstar = -1;
        for (int b = NBINS - 1; b >= 0; b--) {
            suf += h[b];
            if (suf >= 512) { bstar = b; break; }
        }
        if (bstar < 0) bstar = 0;
        int ba = bstar > 0 ? bstar - 1 : 0;
        unsigned cnt = suf + ((ba < bstar) ? h[ba] : 0u);
        while (cnt > CAP && ba < NBINS - 1) {
            cnt -= h[ba];
            ba++;
        }
        float thr = (float)ba * (1.0f / 1024.0f);
        if (thr < 1e-30f) thr = 1e-30f;
        g_thr = thr;
        g_skip = 0;
        g_ccount = 0;
    }
}

// Fallback collect — SMALL GRID + s-loop (cheap when idle/skipped).
__global__ __launch_bounds__(256) void collect_kernel(const float* __restrict__ aff) {
    if (g_skip) return;
    __shared__ float rows[KNB][2048];
    __shared__ int   s_sidx[KNB];
    int tid = threadIdx.x;
    float thr = g_thr;
    for (int s = blockIdx.x; s < NS; s += gridDim.x) {
        __syncthreads();
        if (tid < KNB) s_sidx[tid] = g_sidx[s * KNB + tid];
        __syncthreads();
#pragma unroll
        for (int i = 0; i < KNB; i++) {
            const float4* srcp = (const float4*)(aff + s_sidx[i] * NR);
            float4* dst = (float4*)rows[i];
            for (int c = tid; c < 512; c += 256) dst[c] = srcp[c];
        }
        float sdv[KNB];
#pragma unroll
        for (int i = 0; i < KNB; i++) sdv[i] = g_sd[s * KNB + i];
        __syncthreads();
        for (int rb = 0; rb < NR; rb += 256) {
            int r = rb + tid;
            float base = aff[s * NR + r];
            float b100 = -100.0f * base;
            float rd[KNB]; int ra[KNB];
#pragma unroll
            for (int j = 0; j < KNB; j++) {
                rd[j] = g_rdT[j * NR + r];
                ra[j] = g_ridxT[j * NR + r];
            }
#pragma unroll
            for (int i = 0; i < KNB; i++) {
#pragma unroll
                for (int j = 0; j < KNB; j++) {
                    float d  = sdv[i] - rd[j];
                    float dd = __fmul_rn(d, d);
                    float bt = __fmaf_rn(dd, b100, base);
                    if (bt >= thr) {
                        float v = __fmul_rn(bt, rows[i][ra[j]]);
                        if (v >= thr && v > 0.0f) {
                            float qq  = __fdiv_rn(dd, SIG2F);
                            float tmp = __fadd_rn(1.0f, -qq);
                            tmp = fmaxf(tmp, 0.0f);
                            float vf = __fmul_rn(__fmul_rn(base, tmp), rows[i][ra[j]]);
                            unsigned pos = atomicAdd(&g_ccount, 1u);
                            if (pos < CAP) {
                                g_cval[pos] = vf;
                                g_cidx[pos] = (s * NR + r) * 25 + i * 5 + j;
                            }
                        }
                    }
                }
            }
        }
    }
}

// Select: refine (exact capacity check) -> dynamic-width bitonic sort
// (value desc, index asc) -> emit f32 indices.
__global__ __launch_bounds__(1024) void select_kernel(float* __restrict__ out,
                                                      int out_size) {
    __shared__ unsigned long long keys[KEYS_CAP];
    __shared__ unsigned h2[1024];
    __shared__ unsigned m2;
    __shared__ float sh_thr2;
    int tid = threadIdx.x;
    unsigned M = g_ccount; if (M > CAP) M = CAP;
    float thr = g_thr;
    h2[tid] = 0;
    if (tid == 0) { m2 = 0; sh_thr2 = -1.0f; }
    __syncthreads();
    if (M > KEYS_CAP) {
        float binw2 = (1.0f - thr) * (1.0f / 1024.0f);
        if (binw2 <= 0.0f) binw2 = 1e-9f;
        for (unsigned c = tid; c < M; c += 1024) {
            float v = g_cval[c];
            int b = (int)((v - thr) / binw2);
            if (b < 0) b = 0;
            if (b > 1023) b = 1023;
            atomicAdd(&h2[b], 1u);
        }
        __syncthreads();
        if (tid == 0) {
            unsigned suf = 0; int b2 = 0;
            for (int b = 1023; b >= 0; b--) {
                suf += h2[b];
                if (suf >= 512) { b2 = b; break; }
            }
            int ba = b2;
            unsigned cnt = suf;
            if (ba > 0 && cnt + h2[ba - 1] <= (unsigned)KEYS_CAP) {
                ba--; cnt += h2[ba];
            }
            while (cnt > (unsigned)KEYS_CAP && ba < 1023) {
                cnt -= h2[ba]; ba++;
            }
            sh_thr2 = thr + (float)ba * binw2;
            if (sh_thr2 < thr) sh_thr2 = thr;
        }
        __syncthreads();
    }
    float thr2 = sh_thr2;   // -1 => keep all
    for (unsigned c = tid; c < M; c += 1024) {
        float v = g_cval[c];
        if (v >= thr2) {
            unsigned p = atomicAdd(&m2, 1u);
            if (p < KEYS_CAP) {
                unsigned idx = (unsigned)g_cidx[c];
                if (idx > MAXIDX) idx = MAXIDX;
                keys[p] = ((unsigned long long)__float_as_uint(v) << 32)
                        | (unsigned long long)(0xFFFFFFFFu - idx);
            }
        }
    }
    __syncthreads();
    unsigned M2 = m2; if (M2 > KEYS_CAP) M2 = KEYS_CAP;
    unsigned SORT = 512;
    while (SORT < M2) SORT <<= 1;           // <= KEYS_CAP since M2 <= KEYS_CAP
    for (unsigned e = M2 + tid; e < SORT; e += 1024) keys[e] = 0ull;
    __syncthreads();
    for (unsigned k = 2; k <= SORT; k <<= 1) {
        for (unsigned jj = k >> 1; jj > 0; jj >>= 1) {
            for (unsigned e = tid; e < SORT; e += 1024) {
                unsigned partner = e ^ jj;
                if (partner > e) {
                    unsigned long long A = keys[e], B = keys[partner];
                    bool desc = ((e & k) == 0);
                    if (desc ? (A < B) : (A > B)) { keys[e] = B; keys[partner] = A; }
                }
            }
            __syncthreads();
        }
    }
    if (tid < 512) {
        unsigned long long key = keys[tid];
        unsigned idx = 0xFFFFFFFFu - (unsigned)(key & 0xFFFFFFFFull);
        if (idx > MAXIDX) idx = MAXIDX;
        int s = (int)(idx / 51200u);  int rem = (int)(idx - (unsigned)s * 51200u);
        int r = rem / 25;             int ij  = rem - r * 25;
        int i = ij / 5;               int j   = ij - i * 5;
        if (s > NS - 1) s = NS - 1;
        if (r > NR - 1) r = NR - 1;
        if (tid < out_size)        out[tid]        = (float)s;
        if (512 + tid < out_size)  out[512 + tid]  = (float)r;
        if (1024 + tid < out_size) out[1024 + tid] = (float)g_sidx[s * KNB + i];
        if (1536 + tid < out_size) out[1536 + tid] = (float)g_ridxT[j * NR + r];
    }
}

extern "C" void kernel_launch(void* const* d_in, const int* in_sizes, int n_in,
                              void* d_out, int out_size) {
    const float *src, *ref, *aff;
    if (in_sizes[0] >= (1 << 20)) {
        aff = (const float*)d_in[0];
        ref = (const float*)d_in[1];
        src = (const float*)d_in[2];
    } else {
        src = (const float*)d_in[0];
        ref = (const float*)d_in[1];
        aff = (const float*)d_in[2];
    }
    float* out = (float*)d_out;

    knn_kernel<<<(NS + NR) / KNN_QPB, 256>>>(src, ref);   // + state reset
    scan1_kernel<<<NS, 256>>>(aff);
    thresh_kernel<<<1, 64>>>();
    hist_low_kernel<<<FB_GRID, 256>>>(aff);   // s-loop; cheap when idle
    thresh2_kernel<<<1, 256>>>();             // cheap when idle
    collect_kernel<<<FB_GRID, 256>>>(aff);    // s-loop; cheap when skipped
    select_kernel<<<1, 1024>>>(out, out_size);
}